// round 9
// baseline (speedup 1.0000x reference)
#include <cuda_runtime.h>
#include <cuda_bf16.h>
#include <cstdint>

#define NN 20000
#define NE 320000

// ---------------- single aligned device scratch ------------------------------
#define OFF_CNT 0
#define SZ_CNT  20480
#define OFF_AGG (OFF_CNT + SZ_CNT)
#define SZ_AGG  (NN * 512)
#define OFF_H1  (OFF_AGG + SZ_AGG)
#define SZ_H1   (NN * 512)
#define OFF_H2  (OFF_H1 + SZ_H1)
#define SZ_H2   (NN * 512)
#define OFF_H3  (OFF_H2 + SZ_H2)
#define SZ_H3   (NN * 1024)
#define OFF_W1L (OFF_H3 + SZ_H3)
#define OFF_W1R (OFF_W1L + 512*256)
#define OFF_W2L (OFF_W1R + 512*256)
#define OFF_W2R (OFF_W2L + 512*512)
#define OFF_W3L (OFF_W2R + 512*512)
#define OFF_W3R (OFF_W3L + 1024*512)
#define OFF_WFC (OFF_W3R + 1024*512)
#define OFF_XC  (OFF_WFC + 512*1024)
#define OFF_RP   (OFF_XC + NN*256)
#define OFF_FILL (OFF_RP + 20512)
#define OFF_CSR  (OFF_FILL + 20480)
#define SZ_TOTAL (OFF_CSR + NE)

__device__ __align__(128) float g_scratch[SZ_TOTAL];

__device__ __forceinline__ float* bufp(int off, const float* ext) {
    return (off >= 0) ? (g_scratch + off) : const_cast<float*>(ext);
}
__device__ __forceinline__ float f2tf(float f) {
    uint32_t r;
    asm("cvt.rna.tf32.f32 %0, %1;" : "=r"(r) : "f"(f));
    return __uint_as_float(r);
}
__device__ __forceinline__ uint32_t smem_u32(const void* p) {
    uint32_t a;
    asm("{ .reg .u64 t; cvta.to.shared.u64 t, %1; cvt.u32.u64 %0, t; }" : "=r"(a) : "l"(p));
    return a;
}

// ---------------- zero (float4) ----------------------------------------------
__global__ void zero_kernel(int off, int n4) {
    float4* p = (float4*)(g_scratch + off);
    int i = blockIdx.x * blockDim.x + threadIdx.x;
    int stride = gridDim.x * blockDim.x;
    float4 z = make_float4(0.f, 0.f, 0.f, 0.f);
    for (; i < n4; i += stride) p[i] = z;
}

// ---------------- degree count (int) -------------------------------------------
__global__ void count_kernel(const int* __restrict__ ei, int E) {
    int* cnt = (int*)(g_scratch + OFF_CNT);
    int i = blockIdx.x * blockDim.x + threadIdx.x;
    int stride = gridDim.x * blockDim.x;
    for (; i < E; i += stride) atomicAdd(&cnt[ei[E + i]], 1);
}

// ---------------- prefix sum over counts -> row_ptr ----------------------------
__global__ void prefix_kernel() {
    __shared__ int sh[1024];
    __shared__ int carry;
    const int tid = threadIdx.x;
    int* rp = (int*)(g_scratch + OFF_RP);
    const int* cnt = (const int*)(g_scratch + OFF_CNT);
    if (tid == 0) { carry = 0; rp[0] = 0; }
    __syncthreads();
    for (int base = 0; base < NN; base += 1024) {
        int i = base + tid;
        int v = (i < NN) ? cnt[i] : 0;
        sh[tid] = v;
        __syncthreads();
        for (int off = 1; off < 1024; off <<= 1) {
            int t = (tid >= off) ? sh[tid - off] : 0;
            __syncthreads();
            sh[tid] += t;
            __syncthreads();
        }
        if (i < NN) rp[i + 1] = carry + sh[tid];
        __syncthreads();
        if (tid == 0) carry += sh[1023];
        __syncthreads();
    }
}

// ---------------- fill CSR ------------------------------------------------------
__global__ void fillcsr_kernel(const int* __restrict__ ei, int E) {
    const int* rp = (const int*)(g_scratch + OFF_RP);
    int* fill = (int*)(g_scratch + OFF_FILL);
    int* csr = (int*)(g_scratch + OFF_CSR);
    int i = blockIdx.x * blockDim.x + threadIdx.x;
    int stride = gridDim.x * blockDim.x;
    for (; i < E; i += stride) {
        int s = ei[i];
        int t = ei[E + i];
        int pos = rp[t] + atomicAdd(&fill[t], 1);
        csr[pos] = s;
    }
}

// ---------------- gather-mean (warp per node) -----------------------------------
__global__ void gather_kernel(int xoff, const float* __restrict__ xext, int d) {
    const float* x = bufp(xoff, xext);
    float* agg = g_scratch + OFF_AGG;
    const int* rp = (const int*)(g_scratch + OFF_RP);
    const int* csr = (const int*)(g_scratch + OFF_CSR);
    int node = (blockIdx.x * blockDim.x + threadIdx.x) >> 5;
    int lane = threadIdx.x & 31;
    if (node >= NN) return;
    int beg = rp[node], end = rp[node + 1];
    const int nv = d >> 7;

    float4 acc[4];
#pragma unroll
    for (int v = 0; v < 4; v++) acc[v] = make_float4(0.f, 0.f, 0.f, 0.f);

    int e = beg;
    for (; e + 1 < end; e += 2) {
        const float* x0 = x + (size_t)csr[e] * d;
        const float* x1 = x + (size_t)csr[e + 1] * d;
#pragma unroll 4
        for (int v = 0; v < nv; v++) {
            float4 a = *(const float4*)(x0 + lane * 4 + v * 128);
            float4 b = *(const float4*)(x1 + lane * 4 + v * 128);
            acc[v].x += a.x + b.x; acc[v].y += a.y + b.y;
            acc[v].z += a.z + b.z; acc[v].w += a.w + b.w;
        }
    }
    if (e < end) {
        const float* x0 = x + (size_t)csr[e] * d;
#pragma unroll 4
        for (int v = 0; v < nv; v++) {
            float4 a = *(const float4*)(x0 + lane * 4 + v * 128);
            acc[v].x += a.x; acc[v].y += a.y; acc[v].z += a.z; acc[v].w += a.w;
        }
    }
    float sc = 1.0f / (float)max(end - beg, 1);
    float* out = agg + (size_t)node * d + lane * 4;
#pragma unroll 4
    for (int v = 0; v < nv; v++) {
        float4 o;
        o.x = f2tf(acc[v].x * sc); o.y = f2tf(acc[v].y * sc);
        o.z = f2tf(acc[v].z * sc); o.w = f2tf(acc[v].w * sc);
        *(float4*)(out + v * 128) = o;
    }
}

// ---------------- weight transpose + tf32 round ---------------------------------
__global__ void transpose_kernel(const float* __restrict__ src, int dstOff, int K, int N) {
    __shared__ float t[32][33];
    int kb = blockIdx.y * 32, nb = blockIdx.x * 32;
    int tx = threadIdx.x, ty = threadIdx.y;
    for (int i = ty; i < 32; i += 8)
        t[i][tx] = src[(size_t)(kb + i) * N + nb + tx];
    __syncthreads();
    float* dst = g_scratch + dstOff;
    for (int i = ty; i < 32; i += 8)
        dst[(size_t)(nb + i) * K + kb + tx] = f2tf(t[tx][i]);
}

// ---------------- tf32-round copy ------------------------------------------------
__global__ void cvt_kernel(const float* __restrict__ src, int dstOff, int n4) {
    float4* dst = (float4*)(g_scratch + dstOff);
    int i = blockIdx.x * blockDim.x + threadIdx.x;
    int stride = gridDim.x * blockDim.x;
    for (; i < n4; i += stride) {
        float4 v = ((const float4*)src)[i];
        v.x = f2tf(v.x); v.y = f2tf(v.y); v.z = f2tf(v.z); v.w = f2tf(v.w);
        dst[i] = v;
    }
}

// ---------------- tf32 mma.sync GEMM, 4-stage cp.async, warp tile 64x64 --------
// CTA tile 128x128, 128 threads = 4 warps (2 M x 2 N), BK=16.
#define BM 128
#define BN 128
#define BKC 16
#define PADR 20
#define NSTG 4
#define STG_F (BM * PADR)
#define SMEM_GEMM (NSTG * STG_F * 2 * 4)

__global__ __launch_bounds__(128)
void gemm_mma(int a1off, const float* a1ext, int a2off, const float* a2ext, int hasA2,
              int b1off, int b2off, const float* __restrict__ bias,
              int coff, float* cext, int M, int N, int K, int doRelu, int doRound) {
    extern __shared__ float sm[];
    float* sA = sm;
    float* sB = sm + NSTG * STG_F;

    const float* A1 = bufp(a1off, a1ext);
    const float* A2 = bufp(a2off, a2ext);
    const float* B1 = g_scratch + b1off;
    const float* B2 = g_scratch + b2off;
    float* C = bufp(coff, cext);

    const int tid = threadIdx.x, wid = tid >> 5, lane = tid & 31;
    const int rowBase = blockIdx.y * BM;
    const int colBase = blockIdx.x * BN;
    const int wm = (wid >> 1) * 64;     // 2 warps in M
    const int wn = (wid & 1) * 64;      // 2 warps in N
    const int lr = tid >> 2;            // 0..31
    const int lc4 = (tid & 3) * 4;      // 0,4,8,12
    const int qrow = lane >> 2;
    const int qcol = lane & 3;

    const uint32_t sAu = smem_u32(sA);
    const uint32_t sBu = smem_u32(sB);

    float acc[4][8][4];
#pragma unroll
    for (int mi = 0; mi < 4; mi++)
#pragma unroll
        for (int ni = 0; ni < 8; ni++)
#pragma unroll
            for (int r = 0; r < 4; r++) acc[mi][ni][r] = 0.f;

    const int Ktot = hasA2 ? 2 * K : K;
    const int nch = Ktot / BKC;

    auto load_stage = [&](int c) {
        int stg = c & (NSTG - 1);
        int k0 = c * BKC;
        const float* A; const float* B; int kk;
        if (k0 < K) { A = A1; B = B1; kk = k0; }
        else        { A = A2; B = B2; kk = k0 - K; }
#pragma unroll
        for (int p = 0; p < 4; p++) {
            int row = lr + p * 32;
            int gm = rowBase + row;
            const float* src = A + (size_t)gm * K + kk + lc4;
            uint32_t dst = sAu + (uint32_t)(stg * STG_F + row * PADR + lc4) * 4u;
            uint32_t sz = (gm < M) ? 16u : 0u;
            asm volatile("cp.async.cg.shared.global [%0], [%1], 16, %2;"
                         :: "r"(dst), "l"(src), "r"(sz));
        }
#pragma unroll
        for (int p = 0; p < 4; p++) {
            int row = lr + p * 32;
            const float* src = B + (size_t)(colBase + row) * K + kk + lc4;
            uint32_t dst = sBu + (uint32_t)(stg * STG_F + row * PADR + lc4) * 4u;
            asm volatile("cp.async.cg.shared.global [%0], [%1], 16, %2;"
                         :: "r"(dst), "l"(src), "r"(16u));
        }
    };

#pragma unroll
    for (int i = 0; i < NSTG - 1; i++) {
        if (i < nch) load_stage(i);
        asm volatile("cp.async.commit_group;" ::: "memory");
    }

    for (int ch = 0; ch < nch; ch++) {
        asm volatile("cp.async.wait_group 2;" ::: "memory");
        __syncthreads();

        int pre = ch + NSTG - 1;
        if (pre < nch) load_stage(pre);
        asm volatile("cp.async.commit_group;" ::: "memory");

        const float* As = sA + (ch & (NSTG - 1)) * STG_F;
        const float* Bs = sB + (ch & (NSTG - 1)) * STG_F;
#pragma unroll
        for (int ks = 0; ks < 2; ks++) {
            const int kof = ks * 8;
            uint32_t af[4][4], bf[8][2];
#pragma unroll
            for (int mi = 0; mi < 4; mi++) {
                int r0 = wm + mi * 16 + qrow;
                int c0 = kof + qcol;
                af[mi][0] = __float_as_uint(As[r0 * PADR + c0]);
                af[mi][1] = __float_as_uint(As[(r0 + 8) * PADR + c0]);
                af[mi][2] = __float_as_uint(As[r0 * PADR + c0 + 4]);
                af[mi][3] = __float_as_uint(As[(r0 + 8) * PADR + c0 + 4]);
            }
#pragma unroll
            for (int ni = 0; ni < 8; ni++) {
                int cn = wn + ni * 8 + qrow;
                int rk = kof + qcol;
                bf[ni][0] = __float_as_uint(Bs[cn * PADR + rk]);
                bf[ni][1] = __float_as_uint(Bs[cn * PADR + rk + 4]);
            }
#pragma unroll
            for (int mi = 0; mi < 4; mi++)
#pragma unroll
                for (int ni = 0; ni < 8; ni++) {
                    asm volatile(
                        "mma.sync.aligned.m16n8k8.row.col.f32.tf32.tf32.f32 "
                        "{%0,%1,%2,%3}, {%4,%5,%6,%7}, {%8,%9}, {%0,%1,%2,%3};"
                        : "+f"(acc[mi][ni][0]), "+f"(acc[mi][ni][1]),
                          "+f"(acc[mi][ni][2]), "+f"(acc[mi][ni][3])
                        : "r"(af[mi][0]), "r"(af[mi][1]), "r"(af[mi][2]), "r"(af[mi][3]),
                          "r"(bf[ni][0]), "r"(bf[ni][1]));
                }
        }
    }

#pragma unroll
    for (int mi = 0; mi < 4; mi++) {
        int gm0 = rowBase + wm + mi * 16 + qrow;
        int gm1 = gm0 + 8;
#pragma unroll
        for (int ni = 0; ni < 8; ni++) {
            int col = colBase + wn + ni * 8 + 2 * qcol;
            float2 bv = *(const float2*)(bias + col);
            float r0 = acc[mi][ni][0] + bv.x;
            float r1 = acc[mi][ni][1] + bv.y;
            float r2 = acc[mi][ni][2] + bv.x;
            float r3 = acc[mi][ni][3] + bv.y;
            if (doRelu) {
                r0 = fmaxf(r0, 0.f); r1 = fmaxf(r1, 0.f);
                r2 = fmaxf(r2, 0.f); r3 = fmaxf(r3, 0.f);
            }
            if (doRound) {
                r0 = f2tf(r0); r1 = f2tf(r1); r2 = f2tf(r2); r3 = f2tf(r3);
            }
            if (gm0 < M) *(float2*)(C + (size_t)gm0 * N + col) = make_float2(r0, r1);
            if (gm1 < M) *(float2*)(C + (size_t)gm1 * N + col) = make_float2(r2, r3);
        }
    }
}

// ---------------- launch --------------------------------------------------------
extern "C" void kernel_launch(void* const* d_in, const int* in_sizes, int n_in,
                              void* d_out, int out_size) {
    const float* x   = (const float*)d_in[0];
    const int*   ei  = (const int*)d_in[1];
    const float* Wl1 = (const float*)d_in[2];
    const float* bl1 = (const float*)d_in[3];
    const float* Wr1 = (const float*)d_in[4];
    const float* Wl2 = (const float*)d_in[5];
    const float* bl2 = (const float*)d_in[6];
    const float* Wr2 = (const float*)d_in[7];
    const float* Wl3 = (const float*)d_in[8];
    const float* bl3 = (const float*)d_in[9];
    const float* Wr3 = (const float*)d_in[10];
    const float* Wfc = (const float*)d_in[11];
    const float* bfc = (const float*)d_in[12];
    float* out = (float*)d_out;

    cudaFuncSetAttribute(gemm_mma, cudaFuncAttributeMaxDynamicSharedMemorySize, SMEM_GEMM);

    const int M = NN, E = NE;
    const int ZT = 256;
    dim3 tb(32, 8);

    transpose_kernel<<<dim3(512/32, 256/32), tb>>>(Wl1, OFF_W1L, 256, 512);
    transpose_kernel<<<dim3(512/32, 256/32), tb>>>(Wr1, OFF_W1R, 256, 512);
    transpose_kernel<<<dim3(512/32, 512/32), tb>>>(Wl2, OFF_W2L, 512, 512);
    transpose_kernel<<<dim3(512/32, 512/32), tb>>>(Wr2, OFF_W2R, 512, 512);
    transpose_kernel<<<dim3(1024/32, 512/32), tb>>>(Wl3, OFF_W3L, 512, 1024);
    transpose_kernel<<<dim3(1024/32, 512/32), tb>>>(Wr3, OFF_W3R, 512, 1024);
    transpose_kernel<<<dim3(512/32, 1024/32), tb>>>(Wfc, OFF_WFC, 1024, 512);
    cvt_kernel<<<1250, 256>>>(x, OFF_XC, NN * 256 / 4);

    zero_kernel<<<(SZ_CNT / 4 + ZT - 1) / ZT, ZT>>>(OFF_CNT, SZ_CNT / 4);
    zero_kernel<<<(20480 / 4 + ZT - 1) / ZT, ZT>>>(OFF_FILL, 20480 / 4);
    count_kernel<<<1250, 256>>>(ei, E);
    prefix_kernel<<<1, 1024>>>();
    fillcsr_kernel<<<1250, 256>>>(ei, E);

    const int gatherBlocks = (NN * 32 + 255) / 256;
    const int gy = (M + BM - 1) / BM;   // 157

    // ---- layer 1: 256 -> 512
    gather_kernel<<<gatherBlocks, 256>>>(-1, x, 256);
    gemm_mma<<<dim3(512 / BN, gy), 128, SMEM_GEMM>>>(
        OFF_AGG, nullptr, OFF_XC, nullptr, 1, OFF_W1L, OFF_W1R, bl1,
        OFF_H1, nullptr, M, 512, 256, 1, 1);

    // ---- layer 2: 512 -> 512
    gather_kernel<<<gatherBlocks, 256>>>(OFF_H1, nullptr, 512);
    gemm_mma<<<dim3(512 / BN, gy), 128, SMEM_GEMM>>>(
        OFF_AGG, nullptr, OFF_H1, nullptr, 1, OFF_W2L, OFF_W2R, bl2,
        OFF_H2, nullptr, M, 512, 512, 1, 1);

    // ---- layer 3: 512 -> 1024
    gather_kernel<<<gatherBlocks, 256>>>(OFF_H2, nullptr, 512);
    gemm_mma<<<dim3(1024 / BN, gy), 128, SMEM_GEMM>>>(
        OFF_AGG, nullptr, OFF_H2, nullptr, 1, OFF_W3L, OFF_W3R, bl3,
        OFF_H3, nullptr, M, 1024, 512, 1, 1);

    // ---- final FC: 1024 -> 512
    gemm_mma<<<dim3(512 / BN, gy), 128, SMEM_GEMM>>>(
        OFF_H3, nullptr, -1, nullptr, 0, OFF_WFC, OFF_WFC, bfc,
        -1, out, M, 512, 1024, 0, 0);
}

// round 10
// speedup vs baseline: 1.0605x; 1.0605x over previous
#include <cuda_runtime.h>
#include <cuda_bf16.h>
#include <cstdint>

#define NN 20000
#define NE 320000

// ---------------- single aligned device scratch ------------------------------
#define OFF_CNT 0
#define SZ_CNT  20480
#define OFF_AGG (OFF_CNT + SZ_CNT)
#define SZ_AGG  (NN * 512)
#define OFF_H1  (OFF_AGG + SZ_AGG)
#define SZ_H1   (NN * 512)
#define OFF_H2  (OFF_H1 + SZ_H1)
#define SZ_H2   (NN * 512)
#define OFF_H3  (OFF_H2 + SZ_H2)
#define SZ_H3   (NN * 1024)
#define OFF_W1L (OFF_H3 + SZ_H3)
#define OFF_W1R (OFF_W1L + 512*256)
#define OFF_W2L (OFF_W1R + 512*256)
#define OFF_W2R (OFF_W2L + 512*512)
#define OFF_W3L (OFF_W2R + 512*512)
#define OFF_W3R (OFF_W3L + 1024*512)
#define OFF_WFC (OFF_W3R + 1024*512)
#define OFF_XC  (OFF_WFC + 512*1024)
#define OFF_RP   (OFF_XC + NN*256)
#define OFF_FILL (OFF_RP + 20512)
#define OFF_CSR  (OFF_FILL + 20480)
#define SZ_TOTAL (OFF_CSR + NE)

__device__ __align__(128) float g_scratch[SZ_TOTAL];

__device__ __forceinline__ float* bufp(int off, const float* ext) {
    return (off >= 0) ? (g_scratch + off) : const_cast<float*>(ext);
}
__device__ __forceinline__ float f2tf(float f) {
    uint32_t r;
    asm("cvt.rna.tf32.f32 %0, %1;" : "=r"(r) : "f"(f));
    return __uint_as_float(r);
}
__device__ __forceinline__ uint32_t smem_u32(const void* p) {
    uint32_t a;
    asm("{ .reg .u64 t; cvta.to.shared.u64 t, %1; cvt.u32.u64 %0, t; }" : "=r"(a) : "l"(p));
    return a;
}

// ---------------- dual-region zero ---------------------------------------------
__global__ void zero2_kernel(int offA, int n4A, int offB, int n4B) {
    int i = blockIdx.x * blockDim.x + threadIdx.x;
    int stride = gridDim.x * blockDim.x;
    float4 z = make_float4(0.f, 0.f, 0.f, 0.f);
    float4* pa = (float4*)(g_scratch + offA);
    float4* pb = (float4*)(g_scratch + offB);
    for (int j = i; j < n4A; j += stride) pa[j] = z;
    for (int j = i; j < n4B; j += stride) pb[j] = z;
}

// ---------------- degree count (int) -------------------------------------------
__global__ void count_kernel(const int* __restrict__ ei, int E) {
    int* cnt = (int*)(g_scratch + OFF_CNT);
    int i = blockIdx.x * blockDim.x + threadIdx.x;
    int stride = gridDim.x * blockDim.x;
    for (; i < E; i += stride) atomicAdd(&cnt[ei[E + i]], 1);
}

// ---------------- prefix sum over counts -> row_ptr ----------------------------
__global__ void prefix_kernel() {
    __shared__ int sh[1024];
    __shared__ int carry;
    const int tid = threadIdx.x;
    int* rp = (int*)(g_scratch + OFF_RP);
    const int* cnt = (const int*)(g_scratch + OFF_CNT);
    if (tid == 0) { carry = 0; rp[0] = 0; }
    __syncthreads();
    for (int base = 0; base < NN; base += 1024) {
        int i = base + tid;
        int v = (i < NN) ? cnt[i] : 0;
        sh[tid] = v;
        __syncthreads();
        for (int off = 1; off < 1024; off <<= 1) {
            int t = (tid >= off) ? sh[tid - off] : 0;
            __syncthreads();
            sh[tid] += t;
            __syncthreads();
        }
        if (i < NN) rp[i + 1] = carry + sh[tid];
        __syncthreads();
        if (tid == 0) carry += sh[1023];
        __syncthreads();
    }
}

// ---------------- fill CSR ------------------------------------------------------
__global__ void fillcsr_kernel(const int* __restrict__ ei, int E) {
    const int* rp = (const int*)(g_scratch + OFF_RP);
    int* fill = (int*)(g_scratch + OFF_FILL);
    int* csr = (int*)(g_scratch + OFF_CSR);
    int i = blockIdx.x * blockDim.x + threadIdx.x;
    int stride = gridDim.x * blockDim.x;
    for (; i < E; i += stride) {
        int s = ei[i];
        int t = ei[E + i];
        int pos = rp[t] + atomicAdd(&fill[t], 1);
        csr[pos] = s;
    }
}

// ---------------- gather-mean (warp per node) -----------------------------------
__global__ void gather_kernel(int xoff, const float* __restrict__ xext, int d) {
    const float* x = bufp(xoff, xext);
    float* agg = g_scratch + OFF_AGG;
    const int* rp = (const int*)(g_scratch + OFF_RP);
    const int* csr = (const int*)(g_scratch + OFF_CSR);
    int node = (blockIdx.x * blockDim.x + threadIdx.x) >> 5;
    int lane = threadIdx.x & 31;
    if (node >= NN) return;
    int beg = rp[node], end = rp[node + 1];
    const int nv = d >> 7;

    float4 acc[4];
#pragma unroll
    for (int v = 0; v < 4; v++) acc[v] = make_float4(0.f, 0.f, 0.f, 0.f);

    int e = beg;
    for (; e + 1 < end; e += 2) {
        const float* x0 = x + (size_t)csr[e] * d;
        const float* x1 = x + (size_t)csr[e + 1] * d;
#pragma unroll 4
        for (int v = 0; v < nv; v++) {
            float4 a = *(const float4*)(x0 + lane * 4 + v * 128);
            float4 b = *(const float4*)(x1 + lane * 4 + v * 128);
            acc[v].x += a.x + b.x; acc[v].y += a.y + b.y;
            acc[v].z += a.z + b.z; acc[v].w += a.w + b.w;
        }
    }
    if (e < end) {
        const float* x0 = x + (size_t)csr[e] * d;
#pragma unroll 4
        for (int v = 0; v < nv; v++) {
            float4 a = *(const float4*)(x0 + lane * 4 + v * 128);
            acc[v].x += a.x; acc[v].y += a.y; acc[v].z += a.z; acc[v].w += a.w;
        }
    }
    float sc = 1.0f / (float)max(end - beg, 1);
    float* out = agg + (size_t)node * d + lane * 4;
#pragma unroll 4
    for (int v = 0; v < nv; v++) {
        float4 o;
        o.x = f2tf(acc[v].x * sc); o.y = f2tf(acc[v].y * sc);
        o.z = f2tf(acc[v].z * sc); o.w = f2tf(acc[v].w * sc);
        *(float4*)(out + v * 128) = o;
    }
}

// ---------------- merged weight transpose (+tf32): all 7 matrices in 1 launch ---
// 32x32 tiles; block -> (matrix, tile) via cumulative table. 2304 blocks total.
__global__ void transall_kernel(const float* __restrict__ W1l, const float* __restrict__ W1r,
                                const float* __restrict__ W2l, const float* __restrict__ W2r,
                                const float* __restrict__ W3l, const float* __restrict__ W3r,
                                const float* __restrict__ Wfc) {
    __shared__ float t[32][33];
    int b = blockIdx.x;
    const float* src; int dstOff, K, N, lt;
    if      (b < 128)  { src = W1l; dstOff = OFF_W1L; K = 256;  N = 512;  lt = b; }
    else if (b < 256)  { src = W1r; dstOff = OFF_W1R; K = 256;  N = 512;  lt = b - 128; }
    else if (b < 512)  { src = W2l; dstOff = OFF_W2L; K = 512;  N = 512;  lt = b - 256; }
    else if (b < 768)  { src = W2r; dstOff = OFF_W2R; K = 512;  N = 512;  lt = b - 512; }
    else if (b < 1280) { src = W3l; dstOff = OFF_W3L; K = 512;  N = 1024; lt = b - 768; }
    else if (b < 1792) { src = W3r; dstOff = OFF_W3R; K = 512;  N = 1024; lt = b - 1280; }
    else               { src = Wfc; dstOff = OFF_WFC; K = 1024; N = 512;  lt = b - 1792; }
    int ntx = N >> 5;
    int nb = (lt % ntx) * 32, kb = (lt / ntx) * 32;
    int tx = threadIdx.x, ty = threadIdx.y;   // block (32,8)
    for (int i = ty; i < 32; i += 8)
        t[i][tx] = src[(size_t)(kb + i) * N + nb + tx];
    __syncthreads();
    float* dst = g_scratch + dstOff;
    for (int i = ty; i < 32; i += 8)
        dst[(size_t)(nb + i) * K + kb + tx] = f2tf(t[tx][i]);
}

// ---------------- tf32-round copy ------------------------------------------------
__global__ void cvt_kernel(const float* __restrict__ src, int dstOff, int n4) {
    float4* dst = (float4*)(g_scratch + dstOff);
    int i = blockIdx.x * blockDim.x + threadIdx.x;
    int stride = gridDim.x * blockDim.x;
    for (; i < n4; i += stride) {
        float4 v = ((const float4*)src)[i];
        v.x = f2tf(v.x); v.y = f2tf(v.y); v.z = f2tf(v.z); v.w = f2tf(v.w);
        dst[i] = v;
    }
}

// ---------------- tf32 mma.sync GEMM, 4-stage cp.async (R8 config) -------------
// CTA tile 128x128, 256 threads = 8 warps (2 M x 4 N), warp tile 64x32, BK=16.
#define BM 128
#define BN 128
#define BKC 16
#define PADR 20
#define NSTG 4
#define STG_F (BM * PADR)
#define SMEM_GEMM (NSTG * STG_F * 2 * 4)

__global__ __launch_bounds__(256)
void gemm_mma(int a1off, const float* a1ext, int a2off, const float* a2ext, int hasA2,
              int b1off, int b2off, const float* __restrict__ bias,
              int coff, float* cext, int M, int N, int K, int doRelu, int doRound) {
    extern __shared__ float sm[];
    float* sA = sm;
    float* sB = sm + NSTG * STG_F;

    const float* A1 = bufp(a1off, a1ext);
    const float* A2 = bufp(a2off, a2ext);
    const float* B1 = g_scratch + b1off;
    const float* B2 = g_scratch + b2off;
    float* C = bufp(coff, cext);

    const int tid = threadIdx.x, wid = tid >> 5, lane = tid & 31;
    const int rowBase = blockIdx.y * BM;
    const int colBase = blockIdx.x * BN;
    const int wm = (wid >> 2) * 64;
    const int wn = (wid & 3) * 32;
    const int lr = tid >> 2;
    const int lc4 = (tid & 3) * 4;
    const int qrow = lane >> 2;
    const int qcol = lane & 3;

    const uint32_t sAu = smem_u32(sA);
    const uint32_t sBu = smem_u32(sB);

    float acc[4][4][4];
#pragma unroll
    for (int mi = 0; mi < 4; mi++)
#pragma unroll
        for (int ni = 0; ni < 4; ni++)
#pragma unroll
            for (int r = 0; r < 4; r++) acc[mi][ni][r] = 0.f;

    const int Ktot = hasA2 ? 2 * K : K;
    const int nch = Ktot / BKC;

    auto load_stage = [&](int c) {
        int stg = c & (NSTG - 1);
        int k0 = c * BKC;
        const float* A; const float* B; int kk;
        if (k0 < K) { A = A1; B = B1; kk = k0; }
        else        { A = A2; B = B2; kk = k0 - K; }
#pragma unroll
        for (int p = 0; p < 2; p++) {
            int row = lr + p * 64;
            int gm = rowBase + row;
            const float* src = A + (size_t)gm * K + kk + lc4;
            uint32_t dst = sAu + (uint32_t)(stg * STG_F + row * PADR + lc4) * 4u;
            uint32_t sz = (gm < M) ? 16u : 0u;
            asm volatile("cp.async.cg.shared.global [%0], [%1], 16, %2;"
                         :: "r"(dst), "l"(src), "r"(sz));
        }
#pragma unroll
        for (int p = 0; p < 2; p++) {
            int row = lr + p * 64;
            const float* src = B + (size_t)(colBase + row) * K + kk + lc4;
            uint32_t dst = sBu + (uint32_t)(stg * STG_F + row * PADR + lc4) * 4u;
            asm volatile("cp.async.cg.shared.global [%0], [%1], 16, %2;"
                         :: "r"(dst), "l"(src), "r"(16u));
        }
    };

#pragma unroll
    for (int i = 0; i < NSTG - 1; i++) {
        if (i < nch) load_stage(i);
        asm volatile("cp.async.commit_group;" ::: "memory");
    }

    for (int ch = 0; ch < nch; ch++) {
        asm volatile("cp.async.wait_group 2;" ::: "memory");
        __syncthreads();

        int pre = ch + NSTG - 1;
        if (pre < nch) load_stage(pre);
        asm volatile("cp.async.commit_group;" ::: "memory");

        const float* As = sA + (ch & (NSTG - 1)) * STG_F;
        const float* Bs = sB + (ch & (NSTG - 1)) * STG_F;
#pragma unroll
        for (int ks = 0; ks < 2; ks++) {
            const int kof = ks * 8;
            uint32_t af[4][4], bf[4][2];
#pragma unroll
            for (int mi = 0; mi < 4; mi++) {
                int r0 = wm + mi * 16 + qrow;
                int c0 = kof + qcol;
                af[mi][0] = __float_as_uint(As[r0 * PADR + c0]);
                af[mi][1] = __float_as_uint(As[(r0 + 8) * PADR + c0]);
                af[mi][2] = __float_as_uint(As[r0 * PADR + c0 + 4]);
                af[mi][3] = __float_as_uint(As[(r0 + 8) * PADR + c0 + 4]);
            }
#pragma unroll
            for (int ni = 0; ni < 4; ni++) {
                int cn = wn + ni * 8 + qrow;
                int rk = kof + qcol;
                bf[ni][0] = __float_as_uint(Bs[cn * PADR + rk]);
                bf[ni][1] = __float_as_uint(Bs[cn * PADR + rk + 4]);
            }
#pragma unroll
            for (int mi = 0; mi < 4; mi++)
#pragma unroll
                for (int ni = 0; ni < 4; ni++) {
                    asm volatile(
                        "mma.sync.aligned.m16n8k8.row.col.f32.tf32.tf32.f32 "
                        "{%0,%1,%2,%3}, {%4,%5,%6,%7}, {%8,%9}, {%0,%1,%2,%3};"
                        : "+f"(acc[mi][ni][0]), "+f"(acc[mi][ni][1]),
                          "+f"(acc[mi][ni][2]), "+f"(acc[mi][ni][3])
                        : "r"(af[mi][0]), "r"(af[mi][1]), "r"(af[mi][2]), "r"(af[mi][3]),
                          "r"(bf[ni][0]), "r"(bf[ni][1]));
                }
        }
    }

#pragma unroll
    for (int mi = 0; mi < 4; mi++) {
        int gm0 = rowBase + wm + mi * 16 + qrow;
        int gm1 = gm0 + 8;
#pragma unroll
        for (int ni = 0; ni < 4; ni++) {
            int col = colBase + wn + ni * 8 + 2 * qcol;
            float2 bv = *(const float2*)(bias + col);
            float r0 = acc[mi][ni][0] + bv.x;
            float r1 = acc[mi][ni][1] + bv.y;
            float r2 = acc[mi][ni][2] + bv.x;
            float r3 = acc[mi][ni][3] + bv.y;
            if (doRelu) {
                r0 = fmaxf(r0, 0.f); r1 = fmaxf(r1, 0.f);
                r2 = fmaxf(r2, 0.f); r3 = fmaxf(r3, 0.f);
            }
            if (doRound) {
                r0 = f2tf(r0); r1 = f2tf(r1); r2 = f2tf(r2); r3 = f2tf(r3);
            }
            if (gm0 < M) *(float2*)(C + (size_t)gm0 * N + col) = make_float2(r0, r1);
            if (gm1 < M) *(float2*)(C + (size_t)gm1 * N + col) = make_float2(r2, r3);
        }
    }
}

// ---------------- launch --------------------------------------------------------
extern "C" void kernel_launch(void* const* d_in, const int* in_sizes, int n_in,
                              void* d_out, int out_size) {
    const float* x   = (const float*)d_in[0];
    const int*   ei  = (const int*)d_in[1];
    const float* Wl1 = (const float*)d_in[2];
    const float* bl1 = (const float*)d_in[3];
    const float* Wr1 = (const float*)d_in[4];
    const float* Wl2 = (const float*)d_in[5];
    const float* bl2 = (const float*)d_in[6];
    const float* Wr2 = (const float*)d_in[7];
    const float* Wl3 = (const float*)d_in[8];
    const float* bl3 = (const float*)d_in[9];
    const float* Wr3 = (const float*)d_in[10];
    const float* Wfc = (const float*)d_in[11];
    const float* bfc = (const float*)d_in[12];
    float* out = (float*)d_out;

    cudaFuncSetAttribute(gemm_mma, cudaFuncAttributeMaxDynamicSharedMemorySize, SMEM_GEMM);

    const int M = NN, E = NE;
    dim3 tb(32, 8);

    // all weight transposes in one launch; x tf32 copy; CSR build
    transall_kernel<<<2304, tb>>>(Wl1, Wr1, Wl2, Wr2, Wl3, Wr3, Wfc);
    cvt_kernel<<<1250, 256>>>(x, OFF_XC, NN * 256 / 4);

    zero2_kernel<<<40, 256>>>(OFF_CNT, SZ_CNT / 4, OFF_FILL, 20480 / 4);
    count_kernel<<<1250, 256>>>(ei, E);
    prefix_kernel<<<1, 1024>>>();
    fillcsr_kernel<<<1250, 256>>>(ei, E);

    const int gatherBlocks = (NN * 32 + 255) / 256;
    const int gy = (M + BM - 1) / BM;   // 157

    // ---- layer 1: 256 -> 512
    gather_kernel<<<gatherBlocks, 256>>>(-1, x, 256);
    gemm_mma<<<dim3(512 / BN, gy), 256, SMEM_GEMM>>>(
        OFF_AGG, nullptr, OFF_XC, nullptr, 1, OFF_W1L, OFF_W1R, bl1,
        OFF_H1, nullptr, M, 512, 256, 1, 1);

    // ---- layer 2: 512 -> 512
    gather_kernel<<<gatherBlocks, 256>>>(OFF_H1, nullptr, 512);
    gemm_mma<<<dim3(512 / BN, gy), 256, SMEM_GEMM>>>(
        OFF_AGG, nullptr, OFF_H1, nullptr, 1, OFF_W2L, OFF_W2R, bl2,
        OFF_H2, nullptr, M, 512, 512, 1, 1);

    // ---- layer 3: 512 -> 1024
    gather_kernel<<<gatherBlocks, 256>>>(OFF_H2, nullptr, 512);
    gemm_mma<<<dim3(1024 / BN, gy), 256, SMEM_GEMM>>>(
        OFF_AGG, nullptr, OFF_H2, nullptr, 1, OFF_W3L, OFF_W3R, bl3,
        OFF_H3, nullptr, M, 1024, 512, 1, 1);

    // ---- final FC: 1024 -> 512
    gemm_mma<<<dim3(512 / BN, gy), 256, SMEM_GEMM>>>(
        OFF_H3, nullptr, -1, nullptr, 0, OFF_WFC, OFF_WFC, bfc,
        -1, out, M, 512, 1024, 0, 0);
}